// round 9
// baseline (speedup 1.0000x reference)
#include <cuda_runtime.h>
#include <cuda_fp16.h>
#include <cstdint>

// ============================================================================
// PhaseCoherenceComputer: C[bh,q,k] = mean_h cos(phq - phk)
//   = (cos_q @ cos_k^T + sin_q @ sin_k^T) / 64
// 16 GEMMs [2048,128]@[128,2048]^T in fp16 (validated rel_err ~5.6e-5).
// 1/64 folded into A scratch. Scratch row (K=128 fp16): cos[0:64] sin[64:128].
// R9 = R8 (74.0us) + per-warp smem-staged epilogue (syncwarp only, NO CTA
// barriers): each warp stages 16x32 fp32 chunks in a private buffer and
// streams full 128B lines via st.global.cs.v4. Cuts epilogue L1 wavefronts 4x.
// ============================================================================

#define NBH 16
#define SEQ 2048
#define NH  64
#define KS  128          // scratch K width (cos 64 | sin 64)
#define BM  128
#define BN  128
#define BK  64
#define KITERS 2

// ---------------- scratch (device globals; no allocation APIs) --------------
__device__ __align__(16) __half gA[NBH * SEQ * KS];   // 8 MB (pre-scaled 1/64)
__device__ __align__(16) __half gB[NBH * SEQ * KS];   // 8 MB

__device__ __forceinline__ uint32_t smem_u32(const void* p) {
    uint32_t a;
    asm("{ .reg .u64 t; cvta.to.shared.u64 t, %1; cvt.u32.u64 %0, t; }"
        : "=r"(a) : "l"(p));
    return a;
}

#define CP_ASYNC_16(smem, gptr)                                                \
    asm volatile("cp.async.cg.shared.global [%0], [%1], 16;"                   \
                 :: "r"(smem), "l"(gptr))
#define CP_COMMIT()  asm volatile("cp.async.commit_group;" ::: "memory")
#define CP_WAIT(N)   asm volatile("cp.async.wait_group %0;" :: "n"(N) : "memory")

#define LDSM_X4(r0, r1, r2, r3, addr)                                          \
    asm volatile("ldmatrix.sync.aligned.m8n8.x4.shared.b16 {%0,%1,%2,%3}, [%4];" \
                 : "=r"(r0), "=r"(r1), "=r"(r2), "=r"(r3) : "r"(addr))

#define MMA_F16(c0, c1, c2, c3, a0, a1, a2, a3, b0, b1)                        \
    asm volatile("mma.sync.aligned.m16n8k16.row.col.f32.f16.f16.f32 "          \
                 "{%0,%1,%2,%3}, {%4,%5,%6,%7}, {%8,%9}, {%0,%1,%2,%3};"       \
                 : "+f"(c0), "+f"(c1), "+f"(c2), "+f"(c3)                      \
                 : "r"(a0), "r"(a1), "r"(a2), "r"(a3), "r"(b0), "r"(b1))

#define STG_CS_V4(gptr, x, y, z, w)                                            \
    asm volatile("st.global.cs.v4.f32 [%0], {%1,%2,%3,%4};"                    \
                 :: "l"(gptr), "f"(x), "f"(y), "f"(z), "f"(w) : "memory")

// ============================================================================
// Kernel 1: __sincosf -> fp16 scratch (A pre-scaled 1/NH). 4 harmonics/thread.
// ============================================================================
__global__ void phase_prep_kernel(const float* __restrict__ q,
                                  const float* __restrict__ k)
{
    const int NT = NBH * SEQ * (NH / 4);    // 524288 threads per tensor
    int idx = blockIdx.x * blockDim.x + threadIdx.x;
    if (idx >= 2 * NT) return;
    bool isQ = idx < NT;
    int li  = isQ ? idx : idx - NT;
    int row = li >> 4;
    int h4  = (li & 15) << 2;

    const float4 v = *(const float4*)((isQ ? q : k) + (size_t)row * NH + h4);
    const float sc = isQ ? (1.0f / (float)NH) : 1.0f;

    float s0, c0, s1, c1, s2, c2, s3, c3;
    __sincosf(v.x, &s0, &c0);
    __sincosf(v.y, &s1, &c1);
    __sincosf(v.z, &s2, &c2);
    __sincosf(v.w, &s3, &c3);

    __half2 ca = __floats2half2_rn(c0 * sc, c1 * sc);
    __half2 cb = __floats2half2_rn(c2 * sc, c3 * sc);
    __half2 sa = __floats2half2_rn(s0 * sc, s1 * sc);
    __half2 sb = __floats2half2_rn(s2 * sc, s3 * sc);

    __half* dst = (isQ ? gA : gB) + (size_t)row * KS;
    uint2 uc, us;
    uc.x = *reinterpret_cast<uint32_t*>(&ca);
    uc.y = *reinterpret_cast<uint32_t*>(&cb);
    us.x = *reinterpret_cast<uint32_t*>(&sa);
    us.y = *reinterpret_cast<uint32_t*>(&sb);
    *(uint2*)(dst + h4)      = uc;
    *(uint2*)(dst + 64 + h4) = us;
}

// ============================================================================
// Kernel 2: fp16 mma.sync GEMM, BM=BN=128, BK=64 x2 stages issued up-front,
// one wait+barrier, barrier-free mainloop + per-warp staged .cs epilogue.
// grid = (16,16,16), 256 threads (2x4 warps, 64x32 tiles).
// smem: tiles 64KB | 8 x (16 rows x 36 floats) warp staging buffers 18KB.
// ============================================================================
#define STG_BYTES (2 * BM * BK * 2)           // 32768 (A tile + B tile)
#define TILE_BYTES (KITERS * STG_BYTES)       // 65536
#define WB_STRIDE 36                           // floats per staging row
#define WB_BYTES  (16 * WB_STRIDE * 4)         // 2304 per warp
#define SMEM_TOTAL (TILE_BYTES + 8 * WB_BYTES) // 83968

__global__ void __launch_bounds__(256, 2)
phase_gemm_kernel(float* __restrict__ out)
{
    extern __shared__ char smem[];
    const uint32_t sb = smem_u32(smem);
    const int tid  = threadIdx.x;
    const int wid  = tid >> 5;
    const int lane = tid & 31;
    const int wm   = wid >> 2;          // 0-1
    const int wn   = wid & 3;           // 0-3

    const int nt = blockIdx.x;
    const int mt = blockIdx.y;
    const int bh = blockIdx.z;

    const __half* __restrict__ pA = gA + ((size_t)bh * SEQ + (size_t)mt * BM) * KS;
    const __half* __restrict__ pB = gB + ((size_t)bh * SEQ + (size_t)nt * BN) * KS;

    const int ldRow = tid >> 3;          // base row, +32 stride x4
    const int ldChk = tid & 7;           // 16B chunk in 128B smem row

    uint32_t stSm[4];
    size_t   stGm[4];
#pragma unroll
    for (int t = 0; t < 4; t++) {
        int row = ldRow + t * 32;
        stSm[t] = (uint32_t)(row * 128 + ((ldChk ^ (row & 7)) << 4));
        stGm[t] = (size_t)row * KS + ldChk * 8;
    }

    // ---- issue both K stages up front, single commit ----
#pragma unroll
    for (int s = 0; s < KITERS; s++) {
        uint32_t base = sb + s * STG_BYTES;
        const int off = s * BK;
#pragma unroll
        for (int t = 0; t < 4; t++) {
            CP_ASYNC_16(base + stSm[t],                 pA + stGm[t] + off);
            CP_ASYNC_16(base + (BM * BK * 2) + stSm[t], pB + stGm[t] + off);
        }
    }
    CP_COMMIT();

    // ldmatrix base rows
    const int rl = lane & 15;
    const int hc = lane >> 4;
    uint32_t aRow[4], bRow[2];
#pragma unroll
    for (int mf = 0; mf < 4; mf++) aRow[mf] = (uint32_t)(wm * 64 + mf * 16 + rl);
#pragma unroll
    for (int p = 0; p < 2; p++)   bRow[p]  = (uint32_t)(wn * 32 + p * 16 + rl);

    float acc[4][4][4];
#pragma unroll
    for (int mf = 0; mf < 4; mf++)
#pragma unroll
        for (int nf = 0; nf < 4; nf++)
#pragma unroll
            for (int j = 0; j < 4; j++) acc[mf][nf][j] = 0.0f;

    // ---- single wait + barrier, then barrier-free 8-slice mainloop ----
    CP_WAIT(0);
    __syncthreads();

#pragma unroll
    for (int ki = 0; ki < KITERS; ki++) {
        const uint32_t aBase = sb + ki * STG_BYTES;
        const uint32_t bBase = aBase + BM * BK * 2;
#pragma unroll
        for (int kk = 0; kk < 4; kk++) {
            const int kk2 = kk * 2;
            uint32_t a[4][4];
#pragma unroll
            for (int mf = 0; mf < 4; mf++) {
                uint32_t r = aRow[mf];
                uint32_t addr = aBase + r * 128 + ((((uint32_t)(kk2 + hc)) ^ (r & 7)) << 4);
                LDSM_X4(a[mf][0], a[mf][1], a[mf][2], a[mf][3], addr);
            }
            uint32_t b[4][2];
#pragma unroll
            for (int p = 0; p < 2; p++) {
                uint32_t r = bRow[p];
                uint32_t addr = bBase + r * 128 + ((((uint32_t)(kk2 + hc)) ^ (r & 7)) << 4);
                uint32_t x0, x1, x2, x3;
                LDSM_X4(x0, x1, x2, x3, addr);
                b[p * 2][0]     = x0; b[p * 2][1]     = x2;
                b[p * 2 + 1][0] = x1; b[p * 2 + 1][1] = x3;
            }
#pragma unroll
            for (int mf = 0; mf < 4; mf++)
#pragma unroll
                for (int nf = 0; nf < 4; nf++)
                    MMA_F16(acc[mf][nf][0], acc[mf][nf][1],
                            acc[mf][nf][2], acc[mf][nf][3],
                            a[mf][0], a[mf][1], a[mf][2], a[mf][3],
                            b[nf][0], b[nf][1]);
        }
    }

    // ---- per-warp staged epilogue: syncwarp only, full-line .cs stores ----
    {
        float* wbuf = (float*)(smem + TILE_BYTES + wid * WB_BYTES);
        const int qg   = lane >> 2;          // 0-7
        const int cp2  = (lane & 3) * 2;     // 0,2,4,6
        const int rrow = lane >> 3;          // 0-3 (read-back)
        const int rcol = (lane & 7) * 4;     // 0-28
        float* obase = out + ((size_t)bh * SEQ + (size_t)mt * BM + wm * 64) * SEQ
                           + (size_t)nt * BN + wn * 32;
#pragma unroll
        for (int mf = 0; mf < 4; mf++) {
            // stage 16x32 chunk (rows qg and qg+8) in mma layout
#pragma unroll
            for (int nf = 0; nf < 4; nf++) {
                float* p0 = wbuf + qg * WB_STRIDE + nf * 8 + cp2;
                *(float2*)p0 = make_float2(acc[mf][nf][0], acc[mf][nf][1]);
                *(float2*)(p0 + 8 * WB_STRIDE) =
                    make_float2(acc[mf][nf][2], acc[mf][nf][3]);
            }
            __syncwarp();
            // stream out: 4 iterations x 4 rows, each row a full 128B line
#pragma unroll
            for (int t = 0; t < 4; t++) {
                const int row = t * 4 + rrow;
                const float4 v = *(const float4*)(wbuf + row * WB_STRIDE + rcol);
                STG_CS_V4(obase + (size_t)(mf * 16 + row) * SEQ + rcol,
                          v.x, v.y, v.z, v.w);
            }
            __syncwarp();   // buffer reuse guard for next mf
        }
    }
}

// ============================================================================
// launch
// ============================================================================
extern "C" void kernel_launch(void* const* d_in, const int* in_sizes, int n_in,
                              void* d_out, int out_size)
{
    const float* q = (const float*)d_in[0];
    const float* k = (const float*)d_in[1];
    float* out = (float*)d_out;

    cudaFuncSetAttribute(phase_gemm_kernel,
                         cudaFuncAttributeMaxDynamicSharedMemorySize, SMEM_TOTAL);

    const int NT = NBH * SEQ * (NH / 4);
    int threads = 256;
    int blocks = (2 * NT + threads - 1) / threads;
    phase_prep_kernel<<<blocks, threads>>>(q, k);

    dim3 grid(SEQ / BN, SEQ / BM, NBH);   // (16,16,16)
    phase_gemm_kernel<<<grid, 256, SMEM_TOTAL>>>(out);
}

// round 10
// speedup vs baseline: 1.0056x; 1.0056x over previous
#include <cuda_runtime.h>
#include <cuda_fp16.h>
#include <cstdint>

// ============================================================================
// PhaseCoherenceComputer: C[bh,q,k] = mean_h cos(phq - phk)
//   = (cos_q @ cos_k^T + sin_q @ sin_k^T) / 64
// 16 GEMMs [2048,128]@[128,2048]^T in fp16 (validated rel_err ~5.6e-5).
// 1/64 folded into A scratch. Scratch row (K=128 fp16): cos[0:64] sin[64:128].
// R10 = R8 (74.0us best) + explicit software pipelining: fragment registers
// double-buffered across the 8 k-slices (LDSMs of slice s+1 issued before the
// MMAs of slice s). Epilogue = direct .cs scatter (staging tried 3x, never won).
// ============================================================================

#define NBH 16
#define SEQ 2048
#define NH  64
#define KS  128          // scratch K width (cos 64 | sin 64)
#define BM  128
#define BN  128
#define BK  64
#define KITERS 2

// ---------------- scratch (device globals; no allocation APIs) --------------
__device__ __align__(16) __half gA[NBH * SEQ * KS];   // 8 MB (pre-scaled 1/64)
__device__ __align__(16) __half gB[NBH * SEQ * KS];   // 8 MB

__device__ __forceinline__ uint32_t smem_u32(const void* p) {
    uint32_t a;
    asm("{ .reg .u64 t; cvta.to.shared.u64 t, %1; cvt.u32.u64 %0, t; }"
        : "=r"(a) : "l"(p));
    return a;
}

#define CP_ASYNC_16(smem, gptr)                                                \
    asm volatile("cp.async.cg.shared.global [%0], [%1], 16;"                   \
                 :: "r"(smem), "l"(gptr))
#define CP_COMMIT()  asm volatile("cp.async.commit_group;" ::: "memory")
#define CP_WAIT(N)   asm volatile("cp.async.wait_group %0;" :: "n"(N) : "memory")

#define LDSM_X4(r0, r1, r2, r3, addr)                                          \
    asm volatile("ldmatrix.sync.aligned.m8n8.x4.shared.b16 {%0,%1,%2,%3}, [%4];" \
                 : "=r"(r0), "=r"(r1), "=r"(r2), "=r"(r3) : "r"(addr))

#define MMA_F16(c0, c1, c2, c3, a0, a1, a2, a3, b0, b1)                        \
    asm volatile("mma.sync.aligned.m16n8k16.row.col.f32.f16.f16.f32 "          \
                 "{%0,%1,%2,%3}, {%4,%5,%6,%7}, {%8,%9}, {%0,%1,%2,%3};"       \
                 : "+f"(c0), "+f"(c1), "+f"(c2), "+f"(c3)                      \
                 : "r"(a0), "r"(a1), "r"(a2), "r"(a3), "r"(b0), "r"(b1))

#define STG_CS_V2(gptr, x, y)                                                  \
    asm volatile("st.global.cs.v2.f32 [%0], {%1,%2};"                          \
                 :: "l"(gptr), "f"(x), "f"(y) : "memory")

// ============================================================================
// Kernel 1: __sincosf -> fp16 scratch (A pre-scaled 1/NH). 4 harmonics/thread.
// ============================================================================
__global__ void phase_prep_kernel(const float* __restrict__ q,
                                  const float* __restrict__ k)
{
    const int NT = NBH * SEQ * (NH / 4);    // 524288 threads per tensor
    int idx = blockIdx.x * blockDim.x + threadIdx.x;
    if (idx >= 2 * NT) return;
    bool isQ = idx < NT;
    int li  = isQ ? idx : idx - NT;
    int row = li >> 4;
    int h4  = (li & 15) << 2;

    const float4 v = *(const float4*)((isQ ? q : k) + (size_t)row * NH + h4);
    const float sc = isQ ? (1.0f / (float)NH) : 1.0f;

    float s0, c0, s1, c1, s2, c2, s3, c3;
    __sincosf(v.x, &s0, &c0);
    __sincosf(v.y, &s1, &c1);
    __sincosf(v.z, &s2, &c2);
    __sincosf(v.w, &s3, &c3);

    __half2 ca = __floats2half2_rn(c0 * sc, c1 * sc);
    __half2 cb = __floats2half2_rn(c2 * sc, c3 * sc);
    __half2 sa = __floats2half2_rn(s0 * sc, s1 * sc);
    __half2 sb = __floats2half2_rn(s2 * sc, s3 * sc);

    __half* dst = (isQ ? gA : gB) + (size_t)row * KS;
    uint2 uc, us;
    uc.x = *reinterpret_cast<uint32_t*>(&ca);
    uc.y = *reinterpret_cast<uint32_t*>(&cb);
    us.x = *reinterpret_cast<uint32_t*>(&sa);
    us.y = *reinterpret_cast<uint32_t*>(&sb);
    *(uint2*)(dst + h4)      = uc;
    *(uint2*)(dst + 64 + h4) = us;
}

// ============================================================================
// Kernel 2: fp16 mma.sync GEMM, BM=BN=128, BK=64 x2 stages issued up-front,
// single wait+barrier, software-pipelined 8-slice mainloop (double-buffered
// fragments), direct .cs scatter epilogue.
// grid = (16,16,16), 256 threads (2x4 warps, 64x32 tiles).
// ============================================================================
#define STG_BYTES (2 * BM * BK * 2)           // 32768 (A tile + B tile)
#define SMEM_TOTAL (KITERS * STG_BYTES)       // 65536

__global__ void __launch_bounds__(256, 2)
phase_gemm_kernel(float* __restrict__ out)
{
    extern __shared__ char smem[];
    const uint32_t sb = smem_u32(smem);
    const int tid  = threadIdx.x;
    const int wid  = tid >> 5;
    const int lane = tid & 31;
    const int wm   = wid >> 2;          // 0-1
    const int wn   = wid & 3;           // 0-3

    const int nt = blockIdx.x;
    const int mt = blockIdx.y;
    const int bh = blockIdx.z;

    const __half* __restrict__ pA = gA + ((size_t)bh * SEQ + (size_t)mt * BM) * KS;
    const __half* __restrict__ pB = gB + ((size_t)bh * SEQ + (size_t)nt * BN) * KS;

    const int ldRow = tid >> 3;          // base row, +32 stride x4
    const int ldChk = tid & 7;           // 16B chunk in 128B smem row

    uint32_t stSm[4];
    size_t   stGm[4];
#pragma unroll
    for (int t = 0; t < 4; t++) {
        int row = ldRow + t * 32;
        stSm[t] = (uint32_t)(row * 128 + ((ldChk ^ (row & 7)) << 4));
        stGm[t] = (size_t)row * KS + ldChk * 8;
    }

    // ---- issue both K stages up front, single commit ----
#pragma unroll
    for (int s = 0; s < KITERS; s++) {
        uint32_t base = sb + s * STG_BYTES;
        const int off = s * BK;
#pragma unroll
        for (int t = 0; t < 4; t++) {
            CP_ASYNC_16(base + stSm[t],                 pA + stGm[t] + off);
            CP_ASYNC_16(base + (BM * BK * 2) + stSm[t], pB + stGm[t] + off);
        }
    }
    CP_COMMIT();

    // ldmatrix base rows
    const int rl = lane & 15;
    const int hc = lane >> 4;
    uint32_t aRow[4], bRow[2];
#pragma unroll
    for (int mf = 0; mf < 4; mf++) aRow[mf] = (uint32_t)(wm * 64 + mf * 16 + rl);
#pragma unroll
    for (int p = 0; p < 2; p++)   bRow[p]  = (uint32_t)(wn * 32 + p * 16 + rl);

    float acc[4][4][4];
#pragma unroll
    for (int mf = 0; mf < 4; mf++)
#pragma unroll
        for (int nf = 0; nf < 4; nf++)
#pragma unroll
            for (int j = 0; j < 4; j++) acc[mf][nf][j] = 0.0f;

    // ---- single wait + barrier ----
    CP_WAIT(0);
    __syncthreads();

    // ---- software-pipelined mainloop over 8 flattened k-slices ----
    // slice s: stage = s>>2, chunk = (s&3)*2 + hc
    uint32_t af[2][4][4];     // [buf][mfrag][4]
    uint32_t bf[2][4][2];     // [buf][nfrag][2]

#define LOAD_FRAGS(buf, s) do {                                                \
        const uint32_t _aB = sb + ((s) >> 2) * STG_BYTES;                      \
        const uint32_t _bB = _aB + BM * BK * 2;                                \
        const uint32_t _ch = (uint32_t)(((s) & 3) * 2 + hc);                   \
        _Pragma("unroll")                                                      \
        for (int mf = 0; mf < 4; mf++) {                                       \
            uint32_t r = aRow[mf];                                             \
            uint32_t sw = (_ch & 8) | ((_ch & 7) ^ (r & 7));                   \
            LDSM_X4(af[buf][mf][0], af[buf][mf][1],                            \
                    af[buf][mf][2], af[buf][mf][3],                            \
                    _aB + r * 128 + (sw << 4));                                \
        }                                                                      \
        _Pragma("unroll")                                                      \
        for (int p = 0; p < 2; p++) {                                          \
            uint32_t r = bRow[p];                                              \
            uint32_t sw = (_ch & 8) | ((_ch & 7) ^ (r & 7));                   \
            uint32_t x0, x1, x2, x3;                                           \
            LDSM_X4(x0, x1, x2, x3, _bB + r * 128 + (sw << 4));                \
            bf[buf][p * 2][0]     = x0; bf[buf][p * 2][1]     = x2;            \
            bf[buf][p * 2 + 1][0] = x1; bf[buf][p * 2 + 1][1] = x3;            \
        }                                                                      \
    } while (0)

    LOAD_FRAGS(0, 0);

#pragma unroll
    for (int s = 0; s < 8; s++) {
        const int cur = s & 1;
        if (s < 7) LOAD_FRAGS(cur ^ 1, s + 1);   // independent of cur-buf MMAs
#pragma unroll
        for (int mf = 0; mf < 4; mf++)
#pragma unroll
            for (int nf = 0; nf < 4; nf++)
                MMA_F16(acc[mf][nf][0], acc[mf][nf][1],
                        acc[mf][nf][2], acc[mf][nf][3],
                        af[cur][mf][0], af[cur][mf][1],
                        af[cur][mf][2], af[cur][mf][3],
                        bf[cur][nf][0], bf[cur][nf][1]);
    }
#undef LOAD_FRAGS

    // ---- epilogue: direct .cs scatter (scale pre-folded into A) ----
    const int qg  = lane >> 2;
    const int cp2 = (lane & 3) * 2;
    float* obase = out + ((size_t)bh * SEQ + (size_t)mt * BM + wm * 64) * SEQ
                       + (size_t)nt * BN + wn * 32;
#pragma unroll
    for (int mf = 0; mf < 4; mf++) {
#pragma unroll
        for (int nf = 0; nf < 4; nf++) {
            float* p0 = obase + (size_t)(mf * 16 + qg) * SEQ + nf * 8 + cp2;
            STG_CS_V2(p0,           acc[mf][nf][0], acc[mf][nf][1]);
            STG_CS_V2(p0 + 8 * SEQ, acc[mf][nf][2], acc[mf][nf][3]);
        }
    }
}

// ============================================================================
// launch
// ============================================================================
extern "C" void kernel_launch(void* const* d_in, const int* in_sizes, int n_in,
                              void* d_out, int out_size)
{
    const float* q = (const float*)d_in[0];
    const float* k = (const float*)d_in[1];
    float* out = (float*)d_out;

    cudaFuncSetAttribute(phase_gemm_kernel,
                         cudaFuncAttributeMaxDynamicSharedMemorySize, SMEM_TOTAL);

    const int NT = NBH * SEQ * (NH / 4);
    int threads = 256;
    int blocks = (2 * NT + threads - 1) / threads;
    phase_prep_kernel<<<blocks, threads>>>(q, k);

    dim3 grid(SEQ / BN, SEQ / BM, NBH);   // (16,16,16)
    phase_gemm_kernel<<<grid, 256, SMEM_TOTAL>>>(out);
}